// round 2
// baseline (speedup 1.0000x reference)
#include <cuda_runtime.h>
#include <math.h>

#define NN 100000
#define EE 1600000

// ---------------- scratch (device globals; no runtime allocation) ----------------
__device__ int   g_deg[NN];
__device__ int   g_rowp[NN + 1];
__device__ int   g_cur[NN];
__device__ int   g_esrc[EE];
__device__ float g_dinv[NN];
__device__ float g_t [NN * 128];   // fkan output (reused)
__device__ float g_h1[NN * 128];
__device__ float g_h2[NN * 128];
__device__ float g_t2[NN * 64];    // layer-2 fkan output, stride 64 (47 valid cols)

// ---------------- graph preprocessing ----------------
__global__ void k_zero_deg() {
    int i = blockIdx.x * blockDim.x + threadIdx.x;
    if (i < NN) g_deg[i] = 0;
}

__global__ void k_count(const int* __restrict__ ei) {
    int e = blockIdx.x * blockDim.x + threadIdx.x;
    if (e < EE) atomicAdd(&g_deg[ei[EE + e]], 1);
}

// single-block exclusive scan of g_deg -> g_rowp / g_cur
__global__ void k_scan() {
    __shared__ int wsum[32];
    __shared__ int scarry;
    int t = threadIdx.x, lane = t & 31, wid = t >> 5;
    if (t == 0) scarry = 0;
    __syncthreads();
    for (int base = 0; base < NN; base += 1024) {
        int i = base + t;
        int v = (i < NN) ? g_deg[i] : 0;
        int x = v;
        #pragma unroll
        for (int d = 1; d < 32; d <<= 1) {
            int y = __shfl_up_sync(0xffffffffu, x, d);
            if (lane >= d) x += y;
        }
        if (lane == 31) wsum[wid] = x;
        __syncthreads();
        if (wid == 0) {
            int ws = wsum[lane];
            #pragma unroll
            for (int d = 1; d < 32; d <<= 1) {
                int y = __shfl_up_sync(0xffffffffu, ws, d);
                if (lane >= d) ws += y;
            }
            wsum[lane] = ws;
        }
        __syncthreads();
        int carry = scarry;
        int excl = carry + (wid ? wsum[wid - 1] : 0) + (x - v);
        if (i < NN) { g_rowp[i] = excl; g_cur[i] = excl; }
        __syncthreads();
        if (t == 0) scarry = carry + wsum[31];
        __syncthreads();
    }
    if (t == 0) g_rowp[NN] = scarry;
}

__global__ void k_dinv() {
    int i = blockIdx.x * blockDim.x + threadIdx.x;
    if (i < NN) g_dinv[i] = rsqrtf((float)(g_deg[i] + 1));  // +1 self loop
}

__global__ void k_place(const int* __restrict__ ei) {
    int e = blockIdx.x * blockDim.x + threadIdx.x;
    if (e < EE) {
        int d = ei[EE + e];
        int pos = atomicAdd(&g_cur[d], 1);
        g_esrc[pos] = ei[e];
    }
}

// ---------------- fused FastKAN layer ----------------
// out[n,o] = sum_k silu(x[n,k])*Wb[o,k] + sum_{k,g} rbf(z[n,k],g)*Ws[o,k*4+g] + bs[o] + bb[o]
// z = layernorm(x)*gamma+beta,  rbf = exp(-((z-grid_g)*0.75)^2)
template<int DIN, int DOUT, int DOUT_PAD, int TM, int OUT_STRIDE>
__global__ __launch_bounds__(256)
void k_fkan(const float* __restrict__ in0, const float* __restrict__ in1,
            const float* __restrict__ in2,
            const float* __restrict__ lng, const float* __restrict__ lnb,
            const float* __restrict__ Ws,  const float* __restrict__ Wb,
            const float* __restrict__ bs,  const float* __restrict__ bb,
            float* __restrict__ out)
{
    constexpr int KC   = 64;
    constexpr int KTOT = DIN * 5;        // DIN base + DIN*4 spline
    constexpr int RM = 4, RN = 4;
    constexpr int TX = DOUT_PAD / RN;
    constexpr int TY = TM / RM;
    static_assert(TX * TY == 256, "thread tiling");
    constexpr int SXS = DIN + 1;
    constexpr int SWS = DOUT_PAD + 4;
    constexpr int GPR = 256 / TM;        // threads per row for LN reduce

    extern __shared__ float sm[];
    float* sx  = sm;                      // TM * SXS
    float* sW  = sx + TM * SXS;           // KC * SWS
    float* sA  = sW + KC * SWS;           // TM * KC
    float* smu = sA + TM * KC;            // TM
    float* srs = smu + TM;                // TM
    float* sg  = srs + TM;                // DIN
    float* sb  = sg + DIN;                // DIN

    const int t = threadIdx.x;
    const int base = blockIdx.x * TM;

    for (int i = t; i < DIN; i += 256) { sg[i] = lng[i]; sb[i] = lnb[i]; }

    // load input tile (handles 3-way concat for DIN==384)
    for (int e = t; e < TM * DIN; e += 256) {
        int r = e / DIN, c = e - r * DIN;
        int n = base + r;
        float v = 0.f;
        if (n < NN) {
            if (DIN == 384) {
                if (c < 128)      v = in0[n * 128 + c];
                else if (c < 256) v = in1[n * 128 + (c - 128)];
                else              v = in2[n * 128 + (c - 256)];
            } else {
                v = in0[n * DIN + c];
            }
        }
        sx[r * SXS + c] = v;
    }
    __syncthreads();

    // layernorm stats
    {
        int r = t / GPR, l = t % GPR;
        float s = 0.f, s2 = 0.f;
        for (int c = l; c < DIN; c += GPR) {
            float xv = sx[r * SXS + c];
            s += xv; s2 += xv * xv;
        }
        #pragma unroll
        for (int d = 1; d < GPR; d <<= 1) {
            s  += __shfl_xor_sync(0xffffffffu, s,  d);
            s2 += __shfl_xor_sync(0xffffffffu, s2, d);
        }
        if (l == 0) {
            float mu  = s * (1.f / DIN);
            float var = s2 * (1.f / DIN) - mu * mu;
            smu[r] = mu;
            srs[r] = rsqrtf(var + 1e-5f);
        }
    }
    __syncthreads();

    const int ty = t / TX, tx = t - ty * TX;
    float acc[RM][RN];
    #pragma unroll
    for (int r = 0; r < RM; r++)
        #pragma unroll
        for (int c = 0; c < RN; c++) acc[r][c] = 0.f;

    for (int kc = 0; kc < KTOT; kc += KC) {
        // ---- stage W chunk (transposed: sW[k][o]) ----
        const float* wsrc; int stride, koff;
        if (kc < DIN) { wsrc = Wb; stride = DIN;     koff = kc; }
        else          { wsrc = Ws; stride = DIN * 4; koff = kc - DIN; }
        for (int e = t; e < KC * DOUT_PAD; e += 256) {
            int o = e / KC, kk = e - o * KC;
            float w = (o < DOUT) ? wsrc[o * stride + koff + kk] : 0.f;
            sW[kk * SWS + o] = w;
        }
        // ---- stage A chunk (silu base / rbf spline on-the-fly) ----
        for (int e = t; e < TM * KC; e += 256) {
            int r = e / KC, kk = e - r * KC;
            int kg = kc + kk;
            float v;
            if (kg < DIN) {
                float xv = sx[r * SXS + kg];
                v = xv / (1.f + __expf(-xv));
            } else {
                int j = kg - DIN;
                int k2 = j >> 2, g = j & 3;
                float z = (sx[r * SXS + k2] - smu[r]) * srs[r] * sg[k2] + sb[k2];
                float gr = -2.f + (float)g * (4.f / 3.f);
                float u = (z - gr) * 0.75f;   // 1/denom = 3/4
                v = __expf(-u * u);
            }
            sA[r * KC + kk] = v;
        }
        __syncthreads();

        // ---- register-blocked FMA ----
        #pragma unroll 4
        for (int k4 = 0; k4 < KC / 4; k4++) {
            float4 av[RM];
            #pragma unroll
            for (int r = 0; r < RM; r++)
                av[r] = *(const float4*)&sA[(ty * RM + r) * KC + k4 * 4];
            #pragma unroll
            for (int kk = 0; kk < 4; kk++) {
                float4 wv = *(const float4*)&sW[(k4 * 4 + kk) * SWS + tx * RN];
                #pragma unroll
                for (int r = 0; r < RM; r++) {
                    float a = (kk == 0) ? av[r].x : (kk == 1) ? av[r].y
                            : (kk == 2) ? av[r].z : av[r].w;
                    acc[r][0] += a * wv.x;
                    acc[r][1] += a * wv.y;
                    acc[r][2] += a * wv.z;
                    acc[r][3] += a * wv.w;
                }
            }
        }
        __syncthreads();
    }

    #pragma unroll
    for (int r = 0; r < RM; r++) {
        int n = base + ty * RM + r;
        if (n >= NN) continue;
        #pragma unroll
        for (int c = 0; c < RN; c++) {
            int o = tx * RN + c;
            if (o < DOUT)
                out[(long)n * OUT_STRIDE + o] = acc[r][c] + bs[o] + bb[o];
        }
    }
}

// ---------------- aggregation (warp per node, CSR, no atomics) ----------------
__global__ void k_agg128(const float* __restrict__ tin, float* __restrict__ outp,
                         const float* __restrict__ bg) {
    int gw = (blockIdx.x * blockDim.x + threadIdx.x) >> 5;
    int lane = threadIdx.x & 31;
    if (gw >= NN) return;
    int n = gw;
    int beg = g_rowp[n], end = g_rowp[n + 1];
    const float4* t4 = (const float4*)tin;
    float4 a0 = {0, 0, 0, 0}, a1 = {0, 0, 0, 0};
    int j = beg;
    for (; j + 1 < end; j += 2) {
        int s0 = g_esrc[j], s1 = g_esrc[j + 1];
        float w0 = g_dinv[s0], w1 = g_dinv[s1];
        float4 v0 = t4[s0 * 32 + lane];
        float4 v1 = t4[s1 * 32 + lane];
        a0.x += w0 * v0.x; a0.y += w0 * v0.y; a0.z += w0 * v0.z; a0.w += w0 * v0.w;
        a1.x += w1 * v1.x; a1.y += w1 * v1.y; a1.z += w1 * v1.z; a1.w += w1 * v1.w;
    }
    if (j < end) {
        int s0 = g_esrc[j];
        float w0 = g_dinv[s0];
        float4 v0 = t4[s0 * 32 + lane];
        a0.x += w0 * v0.x; a0.y += w0 * v0.y; a0.z += w0 * v0.z; a0.w += w0 * v0.w;
    }
    float dn = g_dinv[n];
    float4 sv = t4[n * 32 + lane];
    float4 bgv = ((const float4*)bg)[lane];
    float4 o;
    o.x = dn * (a0.x + a1.x + dn * sv.x) + bgv.x;
    o.y = dn * (a0.y + a1.y + dn * sv.y) + bgv.y;
    o.z = dn * (a0.z + a1.z + dn * sv.z) + bgv.z;
    o.w = dn * (a0.w + a1.w + dn * sv.w) + bgv.w;
    ((float4*)outp)[n * 32 + lane] = o;
}

__global__ void k_agg47(const float* __restrict__ tin, float* __restrict__ outp,
                        const float* __restrict__ bg) {
    int gw = (blockIdx.x * blockDim.x + threadIdx.x) >> 5;
    int lane = threadIdx.x & 31;
    if (gw >= NN) return;
    int n = gw;
    int beg = g_rowp[n], end = g_rowp[n + 1];
    float a0 = 0.f, a1 = 0.f;
    for (int j = beg; j < end; j++) {
        int s = g_esrc[j];
        float w = g_dinv[s];
        const float* ts = tin + s * 64;
        a0 += w * ts[lane];
        if (lane < 15) a1 += w * ts[32 + lane];
    }
    float dn = g_dinv[n];
    const float* tn = tin + n * 64;
    outp[n * 47 + lane] = dn * (a0 + dn * tn[lane]) + bg[lane];
    if (lane < 15)
        outp[n * 47 + 32 + lane] = dn * (a1 + dn * tn[32 + lane]) + bg[32 + lane];
}

// ---------------- driver ----------------
extern "C" void kernel_launch(void* const* d_in, const int* in_sizes, int n_in,
                              void* d_out, int out_size) {
    const float* x    = (const float*)d_in[0];
    const int*   ei   = (const int*)d_in[1];
    const float* lng0 = (const float*)d_in[2];
    const float* lnb0 = (const float*)d_in[3];
    const float* Ws0  = (const float*)d_in[4];
    const float* bs0  = (const float*)d_in[5];
    const float* Wb0  = (const float*)d_in[6];
    const float* bb0  = (const float*)d_in[7];
    const float* bg0  = (const float*)d_in[8];
    const float* lng1 = (const float*)d_in[9];
    const float* lnb1 = (const float*)d_in[10];
    const float* Ws1  = (const float*)d_in[11];
    const float* bs1  = (const float*)d_in[12];
    const float* Wb1  = (const float*)d_in[13];
    const float* bb1  = (const float*)d_in[14];
    const float* bg1  = (const float*)d_in[15];
    const float* lng2 = (const float*)d_in[16];
    const float* lnb2 = (const float*)d_in[17];
    const float* Ws2  = (const float*)d_in[18];
    const float* bs2  = (const float*)d_in[19];
    const float* Wb2  = (const float*)d_in[20];
    const float* bb2  = (const float*)d_in[21];
    const float* bg2  = (const float*)d_in[22];
    float* outp = (float*)d_out;

    void *pt, *ph1, *ph2, *pt2;
    cudaGetSymbolAddress(&pt,  g_t);
    cudaGetSymbolAddress(&ph1, g_h1);
    cudaGetSymbolAddress(&ph2, g_h2);
    cudaGetSymbolAddress(&pt2, g_t2);

    // dynamic smem sizes
    const int SM_L01 = (32 * 129 + 64 * 132 + 32 * 64 + 32 + 32 + 128 + 128) * 4;   // 59776 B
    const int SM_L2  = (64 * 385 + 64 * 68 + 64 * 64 + 64 + 64 + 384 + 384) * 4;    // 135936 B
    cudaFuncSetAttribute(k_fkan<128, 128, 128, 32, 128>,
                         cudaFuncAttributeMaxDynamicSharedMemorySize, SM_L01);
    cudaFuncSetAttribute(k_fkan<384, 47, 64, 64, 64>,
                         cudaFuncAttributeMaxDynamicSharedMemorySize, SM_L2);

    // graph preprocessing -> CSR + dinv
    k_zero_deg<<<(NN + 255) / 256, 256>>>();
    k_count<<<(EE + 255) / 256, 256>>>(ei);
    k_scan<<<1, 1024>>>();
    k_dinv<<<(NN + 255) / 256, 256>>>();
    k_place<<<(EE + 255) / 256, 256>>>(ei);

    const int FKAN_GRID_01 = (NN + 31) / 32;   // 3125
    const int FKAN_GRID_2  = (NN + 63) / 64;   // 1563
    const int AGG_GRID     = (NN * 32 + 255) / 256;  // warp per node

    // layer 0: x -> h1
    k_fkan<128, 128, 128, 32, 128><<<FKAN_GRID_01, 256, SM_L01>>>(
        x, nullptr, nullptr, lng0, lnb0, Ws0, Wb0, bs0, bb0, (float*)pt);
    k_agg128<<<AGG_GRID, 256>>>((const float*)pt, (float*)ph1, bg0);

    // layer 1: h1 -> h2
    k_fkan<128, 128, 128, 32, 128><<<FKAN_GRID_01, 256, SM_L01>>>(
        (const float*)ph1, nullptr, nullptr, lng1, lnb1, Ws1, Wb1, bs1, bb1, (float*)pt);
    k_agg128<<<AGG_GRID, 256>>>((const float*)pt, (float*)ph2, bg1);

    // layer 2: [x, h1, h2] -> out
    k_fkan<384, 47, 64, 64, 64><<<FKAN_GRID_2, 256, SM_L2>>>(
        x, (const float*)ph1, (const float*)ph2, lng2, lnb2, Ws2, Wb2, bs2, bb2,
        (float*)pt2);
    k_agg47<<<AGG_GRID, 256>>>((const float*)pt2, outp, bg2);
}